// round 1
// baseline (speedup 1.0000x reference)
#include <cuda_runtime.h>
#include <cstdint>
#include <cstddef>

typedef unsigned long long ull;

#define T_STEPS 256
#define BATCH   2048
#define DIN_    128
#define M_TOTAL (T_STEPS * BATCH)   // 524288 rows

// Scratch: zx[m][64] = x-part of the pre-activation, with b+theta folded in.
__device__ float g_zx[(size_t)M_TOTAL * 64];

__device__ __forceinline__ ull ffma2(ull a, ull b, ull c) {
    ull d;
    asm("fma.rn.f32x2 %0, %1, %2, %3;" : "=l"(d) : "l"(a), "l"(b), "l"(c));
    return d;
}

// ---------------------------------------------------------------------------
// Phase 1: zx[m][p] = sum_{k<128} X[m][k] * W[p][k] + bias[p] + theta[p]
// A tile 128x128 in smem, W (64x128) in smem [c][k] stride 130 (conflict-free),
// 8x4 micro-tile per thread, packed f32x2 FMA with even/odd-k halves.
// ---------------------------------------------------------------------------
__global__ __launch_bounds__(256, 2)
void qlstm_phase1(const float* __restrict__ X, const float* __restrict__ W,
                  const float* __restrict__ bias, const float* __restrict__ theta)
{
    extern __shared__ float sm[];
    float* ash = sm;                 // [128][128]
    float* wsh = sm + 128 * 128;     // [64][130]
    float* bt  = wsh + 64 * 130;     // [64]
    const int tid = threadIdx.x;

    // Load A tile (128 rows x 128 k), fully coalesced float4 copy.
    const float4* Xg = reinterpret_cast<const float4*>(X + (size_t)blockIdx.x * (128 * 128));
    float4* A4 = reinterpret_cast<float4*>(ash);
#pragma unroll
    for (int i = 0; i < 16; ++i) A4[tid + 256 * i] = Xg[tid + 256 * i];

    // Load W[p][0:128] (row stride 144 in gmem) -> wsh[c*130 + k]
    for (int i = tid; i < 64 * 128; i += 256) {
        int c = i >> 7, k = i & 127;
        wsh[c * 130 + k] = W[c * 144 + k];
    }
    if (tid < 64) bt[tid] = bias[tid] + theta[tid];
    __syncthreads();

    const int ty = tid >> 4;   // row group: rows ty*8 .. ty*8+7
    const int tx = tid & 15;   // col group: cols tx, tx+16, tx+32, tx+48

    ull acc[8][4];
#pragma unroll
    for (int r = 0; r < 8; ++r)
#pragma unroll
        for (int c = 0; c < 4; ++c) acc[r][c] = 0ull;

#pragma unroll 8
    for (int kp = 0; kp < 64; ++kp) {
        ull w0 = *(const ull*)(wsh + (tx     ) * 130 + 2 * kp);
        ull w1 = *(const ull*)(wsh + (tx + 16) * 130 + 2 * kp);
        ull w2 = *(const ull*)(wsh + (tx + 32) * 130 + 2 * kp);
        ull w3 = *(const ull*)(wsh + (tx + 48) * 130 + 2 * kp);
#pragma unroll
        for (int r = 0; r < 8; ++r) {
            ull a = *(const ull*)(ash + (ty * 8 + r) * 128 + 2 * kp);
            acc[r][0] = ffma2(a, w0, acc[r][0]);
            acc[r][1] = ffma2(a, w1, acc[r][1]);
            acc[r][2] = ffma2(a, w2, acc[r][2]);
            acc[r][3] = ffma2(a, w3, acc[r][3]);
        }
    }

    const float b0 = bt[tx], b1 = bt[tx + 16], b2 = bt[tx + 32], b3 = bt[tx + 48];
    const size_t mbase = (size_t)blockIdx.x * 128 + (size_t)ty * 8;
#pragma unroll
    for (int r = 0; r < 8; ++r) {
        float* o = g_zx + (mbase + r) * 64;
        float2 v0 = *(float2*)&acc[r][0]; o[tx     ] = v0.x + v0.y + b0;
        float2 v1 = *(float2*)&acc[r][1]; o[tx + 16] = v1.x + v1.y + b1;
        float2 v2 = *(float2*)&acc[r][2]; o[tx + 32] = v2.x + v2.y + b2;
        float2 v3 = *(float2*)&acc[r][3]; o[tx + 48] = v3.x + v3.y + b3;
    }
}

// ---------------------------------------------------------------------------
// Phase 2: one warp per batch element, sequential over T.
// Lane l owns gate indices p = l (g = l>>4 in {0,1}, n = l&15) and p = l+32.
// h[n] lives on lane n (n = 0..15); cumprod = width-16 multiplicative scan.
// ---------------------------------------------------------------------------
__global__ __launch_bounds__(256)
void qlstm_phase2(const float* __restrict__ W, float* __restrict__ out)
{
    const int warp = threadIdx.x >> 5;
    const int lane = threadIdx.x & 31;
    const int b    = blockIdx.x * 8 + warp;
    const int n    = lane & 15;
    const bool low = lane < 16;

    // Recurrent weights: Wh[p][j] = W[p*144 + 128 + j]
    float whA[16], whB[16];
    const int pA = lane, pB = lane + 32;
#pragma unroll
    for (int j = 0; j < 16; ++j) {
        whA[j] = W[pA * 144 + 128 + j];
        whB[j] = W[pB * 144 + 128 + j];
    }
    // low lanes: uB = tanh(qB) = 2*sig(2 qB) - 1 ; high lanes: uB = sig(qB)
    const float m2 = low ? 2.f : 1.f;
    const float a0 = low ? -1.f : 0.f;

    float h = 0.f, c = 0.f;
    const float*  zbase = g_zx + (size_t)b * 64 + lane;
    const size_t  TSTR  = (size_t)BATCH * 64;

    // distance-2 prefetch pipeline
    float zA0 = zbase[0];    float zB0 = zbase[32];
    float zA1 = zbase[TSTR]; float zB1 = zbase[TSTR + 32];

    float* outw = out + (size_t)b * 16 + n;

    for (int t = 0; t < T_STEPS; ++t) {
        float z1 = zA0, z2 = zB0;
        zA0 = zA1; zB0 = zB1;
        int t2 = t + 2; if (t2 > T_STEPS - 1) t2 = T_STEPS - 1;
        const size_t off = (size_t)t2 * TSTR;
        zA1 = __ldg(zbase + off);
        zB1 = __ldg(zbase + off + 32);

        // z += Wh * h   (h[j] broadcast from lane j)
#pragma unroll
        for (int j = 0; j < 16; ++j) {
            float hj = __shfl_sync(0xffffffffu, h, j);
            z1 = fmaf(whA[j], hj, z1);
            z2 = fmaf(whB[j], hj, z2);
        }

        float qA = __cosf(z1);
        float qB = __cosf(z2);

        // inclusive cumprod over n within each 16-lane segment
#pragma unroll
        for (int d = 1; d < 16; d <<= 1) {
            float vA = __shfl_up_sync(0xffffffffu, qA, d, 16);
            float vB = __shfl_up_sync(0xffffffffu, qB, d, 16);
            if (n >= d) { qA *= vA; qB *= vB; }
        }

        // gates: low lanes hold (f, g), high lanes hold (i, o)
        float uA = __fdividef(1.f, 1.f + __expf(-qA));       // sigmoid
        float sB = __fdividef(1.f, 1.f + __expf(-m2 * qB));
        float uB = fmaf(sB, m2, a0);                          // tanh / sigmoid

        float iv = __shfl_sync(0xffffffffu, uA, lane | 16);   // i[n]
        float ov = __shfl_sync(0xffffffffu, uB, lane | 16);   // o[n]

        c = fmaf(uA, c, iv * uB);                             // f*c + i*g (valid on low lanes)
        float e2 = __expf(-2.f * c);
        float tc = __fdividef(2.f, 1.f + e2) - 1.f;           // tanh(c)
        float hn = ov * tc;

        if (low) outw[(size_t)t * (BATCH * 16)] = hn;
        h = __shfl_sync(0xffffffffu, hn, n);                  // replicate h[n] to both halves
    }

    if (low) {
        const size_t hx_off = (size_t)T_STEPS * BATCH * 16;
        out[hx_off + (size_t)b * 16 + n] = h;
        out[hx_off + (size_t)BATCH * 16 + (size_t)b * 16 + n] = c;
    }
}

extern "C" void kernel_launch(void* const* d_in, const int* in_sizes, int n_in,
                              void* d_out, int out_size)
{
    const float* X  = (const float*)d_in[0];
    const float* W  = (const float*)d_in[1];
    const float* bb = (const float*)d_in[2];
    const float* th = (const float*)d_in[3];
    float* out = (float*)d_out;

    const int smem = (128 * 128 + 64 * 130 + 64) * (int)sizeof(float);  // 99072 B
    cudaFuncSetAttribute(qlstm_phase1, cudaFuncAttributeMaxDynamicSharedMemorySize, smem);
    qlstm_phase1<<<M_TOTAL / 128, 256, smem>>>(X, W, bb, th);
    qlstm_phase2<<<BATCH / 8, 256>>>(W, out);
}

// round 7
// speedup vs baseline: 1.0250x; 1.0250x over previous
#include <cuda_runtime.h>
#include <cstdint>
#include <cstddef>

#define T_STEPS 256
#define BATCH   2048
#define M_TOTAL (T_STEPS * BATCH)   // 524288 rows
#define AP      132                 // padded smem row (floats), conflict-free fragments

// zx scratch with 3 timesteps of prefetch padding (never read for results)
__device__ float g_zx[((size_t)M_TOTAL + 3 * BATCH) * 64];

__device__ __forceinline__ uint32_t tf32_of(float x) {
    float y; asm("cvt.rna.tf32.f32 %0, %1;" : "=f"(y) : "f"(x));
    return __float_as_uint(y);
}
__device__ __forceinline__ float4 tf32_4(float4 v) {
    v.x = __uint_as_float(tf32_of(v.x)); v.y = __uint_as_float(tf32_of(v.y));
    v.z = __uint_as_float(tf32_of(v.z)); v.w = __uint_as_float(tf32_of(v.w));
    return v;
}

__device__ __forceinline__ void mma_tf32(float c[4], uint32_t a0, uint32_t a1,
                                         uint32_t a2, uint32_t a3,
                                         uint32_t b0, uint32_t b1) {
    asm volatile(
        "mma.sync.aligned.m16n8k8.row.col.f32.tf32.tf32.f32 "
        "{%0,%1,%2,%3}, {%4,%5,%6,%7}, {%8,%9}, {%0,%1,%2,%3};"
        : "+f"(c[0]), "+f"(c[1]), "+f"(c[2]), "+f"(c[3])
        : "r"(a0), "r"(a1), "r"(a2), "r"(a3), "r"(b0), "r"(b1));
}

// ---------------------------------------------------------------------------
// Phase 1: zx[m][p] = sum_k X[m][k]*W[p][k] + bias[p]+theta[p]
// 128x64x128 tile per CTA via mma.sync tf32 m16n8k8 (plain sm_103 PTX).
// Warp w computes rows 16w..16w+15, all 64 output columns.
// ---------------------------------------------------------------------------
__global__ __launch_bounds__(256, 2)
void qlstm_phase1(const float* __restrict__ X, const float* __restrict__ W,
                  const float* __restrict__ bias, const float* __restrict__ theta)
{
    extern __shared__ float sm[];
    float* Ash = sm;                 // [128][AP]
    float* Wsh = sm + 128 * AP;      // [64][AP]   (W[n][k] == B col-major, ldb=K)
    float* bt  = Wsh + 64 * AP;      // [64]
    const int tid = threadIdx.x;

    // A tile: 128 rows x 128 k, coalesced float4, rounded to tf32
    const float4* Xg = reinterpret_cast<const float4*>(X + (size_t)blockIdx.x * (128 * 128));
#pragma unroll
    for (int it = 0; it < 16; ++it) {
        int i = tid + it * 256;
        int row = i >> 5, c4 = i & 31;
        *reinterpret_cast<float4*>(&Ash[row * AP + c4 * 4]) = tf32_4(Xg[i]);
    }
    // W tile: 64 rows (p) x 128 k (gmem row stride 144)
#pragma unroll
    for (int it = 0; it < 8; ++it) {
        int i = tid + it * 256;
        int p = i >> 5, c4 = i & 31;
        float4 v = *reinterpret_cast<const float4*>(W + (size_t)p * 144 + c4 * 4);
        *reinterpret_cast<float4*>(&Wsh[p * AP + c4 * 4]) = tf32_4(v);
    }
    if (tid < 64) bt[tid] = bias[tid] + theta[tid];
    __syncthreads();

    const int w = tid >> 5, lane = tid & 31;
    const int g = lane >> 2, t4 = lane & 3;

    float acc[8][4];
#pragma unroll
    for (int nt = 0; nt < 8; ++nt)
#pragma unroll
        for (int j = 0; j < 4; ++j) acc[nt][j] = 0.f;

    const float* abase = Ash + (16 * w + g) * AP + t4;
    const float* bbase = Wsh + g * AP + t4;

#pragma unroll
    for (int k0 = 0; k0 < 16; ++k0) {
        const float* ap = abase + k0 * 8;
        uint32_t a0 = __float_as_uint(ap[0]);
        uint32_t a1 = __float_as_uint(ap[8 * AP]);
        uint32_t a2 = __float_as_uint(ap[4]);
        uint32_t a3 = __float_as_uint(ap[8 * AP + 4]);
        const float* bp = bbase + k0 * 8;
#pragma unroll
        for (int nt = 0; nt < 8; ++nt) {
            uint32_t b0 = __float_as_uint(bp[nt * 8 * AP]);
            uint32_t b1 = __float_as_uint(bp[nt * 8 * AP + 4]);
            mma_tf32(acc[nt], a0, a1, a2, a3, b0, b1);
        }
    }
    __syncthreads();   // done reading Ash/Wsh; reuse Ash as epilogue buffer

    // bounce through smem (stride 66) for coalesced bias-add store
    float* epi = sm;   // 128*66 floats < Ash size
    {
        const int r0 = 16 * w + g, r1 = r0 + 8;
#pragma unroll
        for (int nt = 0; nt < 8; ++nt) {
            *reinterpret_cast<float2*>(&epi[r0 * 66 + nt * 8 + 2 * t4]) =
                make_float2(acc[nt][0], acc[nt][1]);
            *reinterpret_cast<float2*>(&epi[r1 * 66 + nt * 8 + 2 * t4]) =
                make_float2(acc[nt][2], acc[nt][3]);
        }
    }
    __syncthreads();
    {
        float* og = g_zx + (size_t)blockIdx.x * (128 * 64);
#pragma unroll
        for (int it = 0; it < 32; ++it) {
            int i = tid + it * 256;
            int m = i >> 6, c = i & 63;
            og[i] = epi[m * 66 + c] + bt[c];
        }
    }
}

// ---------------------------------------------------------------------------
// Phase 2: one warp per batch element. Lane l owns gates p=l and p=l+32.
// ---------------------------------------------------------------------------
__global__ __launch_bounds__(256)
void qlstm_phase2(const float* __restrict__ W, float* __restrict__ out)
{
    const int warp = threadIdx.x >> 5;
    const int lane = threadIdx.x & 31;
    const int b    = blockIdx.x * 8 + warp;
    const int n    = lane & 15;
    const bool low = lane < 16;

    float whA[16], whB[16];
#pragma unroll
    for (int j = 0; j < 16; ++j) {
        whA[j] = W[(size_t)lane * 144 + 128 + j];
        whB[j] = W[(size_t)(lane + 32) * 144 + 128 + j];
    }
    const float m2 = low ? 2.f : 1.f;
    const float a0 = low ? -1.f : 0.f;

    float h = 0.f, c = 0.f;
    const float* zp = g_zx + (size_t)b * 64 + lane;
    const size_t TSTR = (size_t)BATCH * 64;

    // distance-3 prefetch (padded scratch: no clamp needed)
    float zA0 = zp[0],        zB0 = zp[32];
    float zA1 = zp[TSTR],     zB1 = zp[TSTR + 32];
    float zA2 = zp[2 * TSTR], zB2 = zp[2 * TSTR + 32];
    const float* zpf = zp + 3 * TSTR;

    float* outp = out + (size_t)b * 16 + n;

    for (int t = 0; t < T_STEPS; ++t) {
        float z1 = zA0, z2 = zB0;
        zA0 = zA1; zB0 = zB1; zA1 = zA2; zB1 = zB2;
        zA2 = __ldg(zpf); zB2 = __ldg(zpf + 32); zpf += TSTR;

        // z += Wh*h : two independent 8-deep fma chains per z
        float p1 = z1, q1 = 0.f, p2 = z2, q2 = 0.f;
#pragma unroll
        for (int j = 0; j < 8; ++j) {
            float hj = __shfl_sync(0xffffffffu, h, j);
            float hk = __shfl_sync(0xffffffffu, h, j + 8);
            p1 = fmaf(whA[j], hj, p1);  q1 = fmaf(whA[j + 8], hk, q1);
            p2 = fmaf(whB[j], hj, p2);  q2 = fmaf(whB[j + 8], hk, q2);
        }
        z1 = p1 + q1; z2 = p2 + q2;

        float qA = __cosf(z1);
        float qB = __cosf(z2);

        // branchless inclusive cumprod over 16-lane segments (FSEL, no BSSY)
#pragma unroll
        for (int d = 1; d < 16; d <<= 1) {
            float vA = __shfl_up_sync(0xffffffffu, qA, d, 16);
            float vB = __shfl_up_sync(0xffffffffu, qB, d, 16);
            qA *= (n >= d) ? vA : 1.0f;
            qB *= (n >= d) ? vB : 1.0f;
        }

        float uA = __fdividef(1.f, 1.f + __expf(-qA));        // sigmoid (f | i)
        float sB = __fdividef(1.f, 1.f + __expf(-m2 * qB));
        float uB = fmaf(sB, m2, a0);                          // tanh(g) | sigmoid(o)

        float iv = __shfl_sync(0xffffffffu, uA, lane | 16);   // i[n]
        float ov = __shfl_sync(0xffffffffu, uB, lane | 16);   // o[n]

        c = fmaf(uA, c, iv * uB);                             // valid on low lanes
        float tc = __fdividef(2.f, 1.f + __expf(-2.f * c)) - 1.f;
        float hn = ov * tc;

        if (low) *outp = hn;
        outp += BATCH * 16;
        h = hn;   // z-accum only sources lanes 0..15 (valid there)
    }

    if (low) {
        const size_t hx = (size_t)T_STEPS * BATCH * 16;
        out[hx + (size_t)b * 16 + n] = h;
        out[hx + (size_t)BATCH * 16 + (size_t)b * 16 + n] = c;
    }
}

extern "C" void kernel_launch(void* const* d_in, const int* in_sizes, int n_in,
                              void* d_out, int out_size)
{
    const float* X  = (const float*)d_in[0];
    const float* W  = (const float*)d_in[1];
    const float* bb = (const float*)d_in[2];
    const float* th = (const float*)d_in[3];
    float* out = (float*)d_out;

    const int smem = (128 * AP + 64 * AP + 64) * (int)sizeof(float);  // ~101.6 KB
    cudaFuncSetAttribute(qlstm_phase1, cudaFuncAttributeMaxDynamicSharedMemorySize, smem);
    qlstm_phase1<<<M_TOTAL / 128, 256, smem>>>(X, W, bb, th);
    qlstm_phase2<<<BATCH / 8, 256>>>(W, out);
}

// round 8
// speedup vs baseline: 1.1743x; 1.1457x over previous
#include <cuda_runtime.h>
#include <cstdint>
#include <cstddef>

#define T_STEPS 256
#define BATCH   2048
#define M_TOTAL (T_STEPS * BATCH)   // 524288 rows
#define AP      132                 // padded smem row (floats), conflict-free fragments

// zx scratch, layout [t][b][n][g] (g fastest), +3 timesteps prefetch padding
__device__ float g_zx[((size_t)M_TOTAL + 3 * BATCH) * 64];

__device__ __forceinline__ uint32_t tf32_of(float x) {
    float y; asm("cvt.rna.tf32.f32 %0, %1;" : "=f"(y) : "f"(x));
    return __float_as_uint(y);
}
__device__ __forceinline__ float4 tf32_4(float4 v) {
    v.x = __uint_as_float(tf32_of(v.x)); v.y = __uint_as_float(tf32_of(v.y));
    v.z = __uint_as_float(tf32_of(v.z)); v.w = __uint_as_float(tf32_of(v.w));
    return v;
}
__device__ __forceinline__ float ex2a(float x) {
    float y; asm("ex2.approx.ftz.f32 %0, %1;" : "=f"(y) : "f"(x)); return y;
}
__device__ __forceinline__ float rcpa(float x) {
    float y; asm("rcp.approx.ftz.f32 %0, %1;" : "=f"(y) : "f"(x)); return y;
}
// sigmoid(x) = 1/(1+2^(-x*log2e)) ; tanh(x) = 2*sigmoid(2x)-1
__device__ __forceinline__ float sig_f(float x) {
    return rcpa(1.f + ex2a(-1.44269504f * x));
}
__device__ __forceinline__ float tanh_f(float x) {
    return fmaf(2.f, rcpa(1.f + ex2a(-2.88539008f * x)), -1.f);
}

__device__ __forceinline__ void mma_tf32(float c[4], uint32_t a0, uint32_t a1,
                                         uint32_t a2, uint32_t a3,
                                         uint32_t b0, uint32_t b1) {
    asm volatile(
        "mma.sync.aligned.m16n8k8.row.col.f32.tf32.tf32.f32 "
        "{%0,%1,%2,%3}, {%4,%5,%6,%7}, {%8,%9}, {%0,%1,%2,%3};"
        : "+f"(c[0]), "+f"(c[1]), "+f"(c[2]), "+f"(c[3])
        : "r"(a0), "r"(a1), "r"(a2), "r"(a3), "r"(b0), "r"(b1));
}

// ---------------------------------------------------------------------------
// Phase 1: zx = X*W^T + bias + theta via mma.sync tf32 m16n8k8.
// Output permuted: row m, output col c' = n*4+g stores z[p = g*16+n].
// ---------------------------------------------------------------------------
__global__ __launch_bounds__(256, 2)
void qlstm_phase1(const float* __restrict__ X, const float* __restrict__ W,
                  const float* __restrict__ bias, const float* __restrict__ theta)
{
    extern __shared__ float sm[];
    float* Ash = sm;                 // [128][AP]
    float* Wsh = sm + 128 * AP;      // [64][AP]
    float* bt  = Wsh + 64 * AP;      // [64], indexed by p
    const int tid = threadIdx.x;

    const float4* Xg = reinterpret_cast<const float4*>(X + (size_t)blockIdx.x * (128 * 128));
#pragma unroll
    for (int it = 0; it < 16; ++it) {
        int i = tid + it * 256;
        int row = i >> 5, c4 = i & 31;
        *reinterpret_cast<float4*>(&Ash[row * AP + c4 * 4]) = tf32_4(Xg[i]);
    }
#pragma unroll
    for (int it = 0; it < 8; ++it) {
        int i = tid + it * 256;
        int p = i >> 5, c4 = i & 31;
        float4 v = *reinterpret_cast<const float4*>(W + (size_t)p * 144 + c4 * 4);
        *reinterpret_cast<float4*>(&Wsh[p * AP + c4 * 4]) = tf32_4(v);
    }
    if (tid < 64) bt[tid] = bias[tid] + theta[tid];
    __syncthreads();

    const int w = tid >> 5, lane = tid & 31;
    const int g = lane >> 2, t4 = lane & 3;

    float acc[8][4];
#pragma unroll
    for (int nt = 0; nt < 8; ++nt)
#pragma unroll
        for (int j = 0; j < 4; ++j) acc[nt][j] = 0.f;

    const float* abase = Ash + (16 * w + g) * AP + t4;
    const float* bbase = Wsh + g * AP + t4;

#pragma unroll
    for (int k0 = 0; k0 < 16; ++k0) {
        const float* ap = abase + k0 * 8;
        uint32_t a0 = __float_as_uint(ap[0]);
        uint32_t a1 = __float_as_uint(ap[8 * AP]);
        uint32_t a2 = __float_as_uint(ap[4]);
        uint32_t a3 = __float_as_uint(ap[8 * AP + 4]);
        const float* bp = bbase + k0 * 8;
#pragma unroll
        for (int nt = 0; nt < 8; ++nt) {
            uint32_t b0 = __float_as_uint(bp[nt * 8 * AP]);
            uint32_t b1 = __float_as_uint(bp[nt * 8 * AP + 4]);
            mma_tf32(acc[nt], a0, a1, a2, a3, b0, b1);
        }
    }
    __syncthreads();   // reuse Ash region as epilogue buffer

    float* epi = sm;   // [128][66]
    {
        const int r0 = 16 * w + g, r1 = r0 + 8;
#pragma unroll
        for (int nt = 0; nt < 8; ++nt) {
            *reinterpret_cast<float2*>(&epi[r0 * 66 + nt * 8 + 2 * t4]) =
                make_float2(acc[nt][0], acc[nt][1]);
            *reinterpret_cast<float2*>(&epi[r1 * 66 + nt * 8 + 2 * t4]) =
                make_float2(acc[nt][2], acc[nt][3]);
        }
    }
    __syncthreads();
    {
        float* og = g_zx + (size_t)blockIdx.x * (128 * 64);
#pragma unroll
        for (int it = 0; it < 32; ++it) {
            int i = tid + it * 256;
            int m = i >> 6, cp = i & 63;                    // output col c' = n*4+g
            int src = ((cp & 3) << 4) | (cp >> 2);          // source col p = g*16+n
            og[i] = epi[m * 66 + src] + bt[src];
        }
    }
}

// ---------------------------------------------------------------------------
// Phase 2: 2 batch elements per warp (16 lanes each). Lane owns n = lane&15
// and ALL 4 gates (p = g*16+n). No cross-half shfls; all lanes valid.
// ---------------------------------------------------------------------------
__global__ __launch_bounds__(256)
void qlstm_phase2(const float* __restrict__ W, float* __restrict__ out)
{
    const int warp = threadIdx.x >> 5;
    const int lane = threadIdx.x & 31;
    const int n    = lane & 15;
    const int b    = 2 * (blockIdx.x * 8 + warp) + (lane >> 4);

    // Recurrent weights: wh[g][j] = W[(g*16+n)*144 + 128 + j]
    float wh[4][16];
#pragma unroll
    for (int g = 0; g < 4; ++g)
#pragma unroll
        for (int j = 0; j < 16; ++j)
            wh[g][j] = W[(size_t)(g * 16 + n) * 144 + 128 + j];

    float h = 0.f, c = 0.f;

    const float4* zp = reinterpret_cast<const float4*>(g_zx) + (size_t)b * 16 + n;
    const size_t S = (size_t)BATCH * 16;     // per-t stride in float4

    float4 f0 = __ldg(zp);
    float4 f1 = __ldg(zp + S);
    float4 f2 = __ldg(zp + 2 * S);
    const float4* zpf = zp + 3 * S;

    float* outp = out + (size_t)b * 16 + n;

    for (int t = 0; t < T_STEPS; ++t) {
        float z0 = f0.x, z1 = f0.y, z2 = f0.z, z3 = f0.w;
        f0 = f1; f1 = f2;
        f2 = __ldg(zpf); zpf += S;

        // z[g] += sum_j wh[g][j] * h[j]  (h[j] broadcast within 16-lane segment)
#pragma unroll
        for (int j = 0; j < 16; ++j) {
            float hj = __shfl_sync(0xffffffffu, h, j, 16);
            z0 = fmaf(wh[0][j], hj, z0);
            z1 = fmaf(wh[1][j], hj, z1);
            z2 = fmaf(wh[2][j], hj, z2);
            z3 = fmaf(wh[3][j], hj, z3);
        }

        float q0 = __cosf(z0), q1 = __cosf(z1), q2 = __cosf(z2), q3 = __cosf(z3);

        // inclusive cumprod over n within 16-lane segments
#pragma unroll
        for (int d = 1; d < 16; d <<= 1) {
            float v0 = __shfl_up_sync(0xffffffffu, q0, d, 16);
            float v1 = __shfl_up_sync(0xffffffffu, q1, d, 16);
            float v2 = __shfl_up_sync(0xffffffffu, q2, d, 16);
            float v3 = __shfl_up_sync(0xffffffffu, q3, d, 16);
            bool p = (n >= d);
            q0 *= p ? v0 : 1.f;
            q1 *= p ? v1 : 1.f;
            q2 *= p ? v2 : 1.f;
            q3 *= p ? v3 : 1.f;
        }

        float fg = sig_f(q0);      // forget
        float ig = sig_f(q1);      // input
        float gg = tanh_f(q2);     // update
        float og = sig_f(q3);      // output

        c = fmaf(fg, c, ig * gg);
        float hn = og * tanh_f(c);

        *outp = hn;                // all 32 lanes store (2 elements)
        outp += BATCH * 16;
        h = hn;
    }

    const size_t hx = (size_t)T_STEPS * BATCH * 16;
    out[hx + (size_t)b * 16 + n] = h;
    out[hx + (size_t)BATCH * 16 + (size_t)b * 16 + n] = c;
}

extern "C" void kernel_launch(void* const* d_in, const int* in_sizes, int n_in,
                              void* d_out, int out_size)
{
    const float* X  = (const float*)d_in[0];
    const float* W  = (const float*)d_in[1];
    const float* bb = (const float*)d_in[2];
    const float* th = (const float*)d_in[3];
    float* out = (float*)d_out;

    const int smem = (128 * AP + 64 * AP + 64) * (int)sizeof(float);  // ~101.6 KB
    cudaFuncSetAttribute(qlstm_phase1, cudaFuncAttributeMaxDynamicSharedMemorySize, smem);
    qlstm_phase1<<<M_TOTAL / 128, 256, smem>>>(X, W, bb, th);
    qlstm_phase2<<<BATCH / 16, 256>>>(W, out);
}

// round 14
// speedup vs baseline: 1.3493x; 1.1490x over previous
#include <cuda_runtime.h>
#include <cstdint>
#include <cstddef>

#define T_STEPS 256
#define BATCH   2048
#define M_TOTAL (T_STEPS * BATCH)   // 524288 rows
#define AP      132                 // padded smem row (floats), conflict-free fragments
#define NW      8                   // warps per CTA (phase2)

// zx scratch, layout [t][b][p] (p = g*16+n), +2 timesteps prefetch padding
__device__ float g_zx[((size_t)M_TOTAL + 3 * BATCH) * 64];

__device__ __forceinline__ uint32_t tf32_of(float x) {
    float y; asm("cvt.rna.tf32.f32 %0, %1;" : "=f"(y) : "f"(x));
    return __float_as_uint(y);
}
__device__ __forceinline__ float4 tf32_4(float4 v) {
    v.x = __uint_as_float(tf32_of(v.x)); v.y = __uint_as_float(tf32_of(v.y));
    v.z = __uint_as_float(tf32_of(v.z)); v.w = __uint_as_float(tf32_of(v.w));
    return v;
}
__device__ __forceinline__ float ex2a(float x) {
    float y; asm("ex2.approx.ftz.f32 %0, %1;" : "=f"(y) : "f"(x)); return y;
}
__device__ __forceinline__ float rcpa(float x) {
    float y; asm("rcp.approx.ftz.f32 %0, %1;" : "=f"(y) : "f"(x)); return y;
}
__device__ __forceinline__ float tanh_f(float x) {
    return fmaf(2.f, rcpa(1.f + ex2a(-2.88539008f * x)), -1.f);
}

__device__ __forceinline__ void mma_tf32(float c[4], uint32_t a0, uint32_t a1,
                                         uint32_t a2, uint32_t a3,
                                         uint32_t b0, uint32_t b1) {
    asm volatile(
        "mma.sync.aligned.m16n8k8.row.col.f32.tf32.tf32.f32 "
        "{%0,%1,%2,%3}, {%4,%5,%6,%7}, {%8,%9}, {%0,%1,%2,%3};"
        : "+f"(c[0]), "+f"(c[1]), "+f"(c[2]), "+f"(c[3])
        : "r"(a0), "r"(a1), "r"(a2), "r"(a3), "r"(b0), "r"(b1));
}

// ---------------------------------------------------------------------------
// Phase 1: zx = X*W^T + bias + theta via mma.sync tf32 m16n8k8.
// ---------------------------------------------------------------------------
__global__ __launch_bounds__(256, 2)
void qlstm_phase1(const float* __restrict__ X, const float* __restrict__ W,
                  const float* __restrict__ bias, const float* __restrict__ theta)
{
    extern __shared__ float sm[];
    float* Ash = sm;                 // [128][AP]
    float* Wsh = sm + 128 * AP;      // [64][AP]
    float* bt  = Wsh + 64 * AP;      // [64]
    const int tid = threadIdx.x;

    const float4* Xg = reinterpret_cast<const float4*>(X + (size_t)blockIdx.x * (128 * 128));
#pragma unroll
    for (int it = 0; it < 16; ++it) {
        int i = tid + it * 256;
        int row = i >> 5, c4 = i & 31;
        *reinterpret_cast<float4*>(&Ash[row * AP + c4 * 4]) = tf32_4(Xg[i]);
    }
#pragma unroll
    for (int it = 0; it < 8; ++it) {
        int i = tid + it * 256;
        int p = i >> 5, c4 = i & 31;
        float4 v = *reinterpret_cast<const float4*>(W + (size_t)p * 144 + c4 * 4);
        *reinterpret_cast<float4*>(&Wsh[p * AP + c4 * 4]) = tf32_4(v);
    }
    if (tid < 64) bt[tid] = bias[tid] + theta[tid];
    __syncthreads();

    const int w = tid >> 5, lane = tid & 31;
    const int g = lane >> 2, t4 = lane & 3;

    float acc[8][4];
#pragma unroll
    for (int nt = 0; nt < 8; ++nt)
#pragma unroll
        for (int j = 0; j < 4; ++j) acc[nt][j] = 0.f;

    const float* abase = Ash + (16 * w + g) * AP + t4;
    const float* bbase = Wsh + g * AP + t4;

#pragma unroll
    for (int k0 = 0; k0 < 16; ++k0) {
        const float* ap = abase + k0 * 8;
        uint32_t a0 = __float_as_uint(ap[0]);
        uint32_t a1 = __float_as_uint(ap[8 * AP]);
        uint32_t a2 = __float_as_uint(ap[4]);
        uint32_t a3 = __float_as_uint(ap[8 * AP + 4]);
        const float* bp = bbase + k0 * 8;
#pragma unroll
        for (int nt = 0; nt < 8; ++nt) {
            uint32_t b0 = __float_as_uint(bp[nt * 8 * AP]);
            uint32_t b1 = __float_as_uint(bp[nt * 8 * AP + 4]);
            mma_tf32(acc[nt], a0, a1, a2, a3, b0, b1);
        }
    }
    __syncthreads();

    float* epi = sm;   // [128][66]
    {
        const int r0 = 16 * w + g, r1 = r0 + 8;
#pragma unroll
        for (int nt = 0; nt < 8; ++nt) {
            *reinterpret_cast<float2*>(&epi[r0 * 66 + nt * 8 + 2 * t4]) =
                make_float2(acc[nt][0], acc[nt][1]);
            *reinterpret_cast<float2*>(&epi[r1 * 66 + nt * 8 + 2 * t4]) =
                make_float2(acc[nt][2], acc[nt][3]);
        }
    }
    __syncthreads();
    {
        float* og = g_zx + (size_t)blockIdx.x * (128 * 64);
#pragma unroll
        for (int it = 0; it < 32; ++it) {
            int i = tid + it * 256;
            int m = i >> 6, c = i & 63;
            og[i] = epi[m * 66 + c] + bt[c];
        }
    }
}

// ---------------------------------------------------------------------------
// Phase 2: 2 batch elements per warp. Lane = e*16 + g*4 + k owns gate g,
// n in {4k..4k+3}. Exchanges via smem (few MIO ops), scan via 3 shfls.
// ---------------------------------------------------------------------------
__global__ __launch_bounds__(256)
void qlstm_phase2(const float* __restrict__ W, float* __restrict__ out)
{
    __shared__ float hbuf[NW][2][16];
    __shared__ float qbuf[NW][2][4][16];

    const int warp = threadIdx.x >> 5;
    const int lane = threadIdx.x & 31;
    const int e    = lane >> 4;          // element within warp
    const int lq   = lane & 15;
    const int g    = lq >> 2;            // gate 0..3
    const int k    = lq & 3;             // owns n = 4k..4k+3
    const int b    = 2 * (blockIdx.x * NW + warp) + e;

    // recurrent weights: wh[i][j] = W[(g*16 + 4k + i)*144 + 128 + j]
    float wh[4][16];
#pragma unroll
    for (int i = 0; i < 4; ++i)
#pragma unroll
        for (int j = 0; j < 16; ++j)
            wh[i][j] = W[(size_t)(g * 16 + 4 * k + i) * 144 + 128 + j];

    // activation constants per lane: gate 2 -> tanh, else sigmoid
    const float m2 = (g == 2) ? 2.f : 1.f;
    const float a0 = (g == 2) ? -1.f : 0.f;
    const float km = -1.44269504f * m2;

    float c0 = 0.f, c1 = 0.f, c2 = 0.f, c3 = 0.f;   // live on g==0 lanes

    hbuf[warp][e][lq] = 0.f;                         // 32 lanes cover [2][16]
    __syncwarp();

    const float4* zp = reinterpret_cast<const float4*>(g_zx) + (size_t)b * 16 + lq;
    const size_t S = (size_t)BATCH * 16;             // per-t stride in float4
    float4 f0 = __ldg(zp);
    float4 f1 = __ldg(zp + S);
    const float4* zpf = zp + 2 * S;

    float* outp = out + (size_t)b * 16 + 4 * k;      // g==0 lanes store here

    for (int t = 0; t < T_STEPS; ++t) {
        // all 16 h values (broadcast LDS)
        const float4* hb = reinterpret_cast<const float4*>(hbuf[warp][e]);
        float4 h0 = hb[0], h1 = hb[1], h2 = hb[2], h3 = hb[3];
        float hh[16] = {h0.x, h0.y, h0.z, h0.w, h1.x, h1.y, h1.z, h1.w,
                        h2.x, h2.y, h2.z, h2.w, h3.x, h3.y, h3.z, h3.w};

        float z0 = f0.x, z1 = f0.y, z2 = f0.z, z3 = f0.w;
        f0 = f1;
        f1 = __ldg(zpf); zpf += S;

        // z[i] += sum_j wh[i][j] * hh[j]   (two 8-chains per output)
        float s0 = 0.f, s1 = 0.f, s2 = 0.f, s3 = 0.f;
#pragma unroll
        for (int j = 0; j < 8; ++j) {
            z0 = fmaf(wh[0][j], hh[j], z0);  s0 = fmaf(wh[0][j + 8], hh[j + 8], s0);
            z1 = fmaf(wh[1][j], hh[j], z1);  s1 = fmaf(wh[1][j + 8], hh[j + 8], s1);
            z2 = fmaf(wh[2][j], hh[j], z2);  s2 = fmaf(wh[2][j + 8], hh[j + 8], s2);
            z3 = fmaf(wh[3][j], hh[j], z3);  s3 = fmaf(wh[3][j + 8], hh[j + 8], s3);
        }
        z0 += s0; z1 += s1; z2 += s2; z3 += s3;

        // in-lane prefix products of cos
        float p0 = __cosf(z0);
        float p1 = p0 * __cosf(z1);
        float p2 = p1 * __cosf(z2);
        float p3 = p2 * __cosf(z3);

        // cross-lane exclusive prefix of lane totals (width-4 groups = one gate)
        float inc = p3;
        float v = __shfl_up_sync(0xffffffffu, inc, 1, 4); inc *= (k >= 1) ? v : 1.f;
        v = __shfl_up_sync(0xffffffffu, inc, 2, 4);       inc *= (k >= 2) ? v : 1.f;
        float ex = __shfl_up_sync(0xffffffffu, inc, 1, 4);
        ex = (k >= 1) ? ex : 1.f;

        float q0 = p0 * ex, q1 = p1 * ex, q2 = p2 * ex, q3 = p3 * ex;

        // activation (sigmoid, or tanh for gate 2, branchless)
        float u0 = fmaf(rcpa(1.f + ex2a(km * q0)), m2, a0);
        float u1 = fmaf(rcpa(1.f + ex2a(km * q1)), m2, a0);
        float u2 = fmaf(rcpa(1.f + ex2a(km * q2)), m2, a0);
        float u3 = fmaf(rcpa(1.f + ex2a(km * q3)), m2, a0);

        *reinterpret_cast<float4*>(&qbuf[warp][e][g][4 * k]) = make_float4(u0, u1, u2, u3);
        __syncwarp();

        if (g == 0) {
            float4 fi = *reinterpret_cast<const float4*>(&qbuf[warp][e][1][4 * k]);
            float4 gu = *reinterpret_cast<const float4*>(&qbuf[warp][e][2][4 * k]);
            float4 oo = *reinterpret_cast<const float4*>(&qbuf[warp][e][3][4 * k]);
            c0 = fmaf(u0, c0, fi.x * gu.x);
            c1 = fmaf(u1, c1, fi.y * gu.y);
            c2 = fmaf(u2, c2, fi.z * gu.z);
            c3 = fmaf(u3, c3, fi.w * gu.w);
            float hn0 = oo.x * tanh_f(c0);
            float hn1 = oo.y * tanh_f(c1);
            float hn2 = oo.z * tanh_f(c2);
            float hn3 = oo.w * tanh_f(c3);
            *reinterpret_cast<float4*>(&hbuf[warp][e][4 * k]) = make_float4(hn0, hn1, hn2, hn3);
            *reinterpret_cast<float4*>(outp + (size_t)t * (BATCH * 16)) =
                make_float4(hn0, hn1, hn2, hn3);
        }
        __syncwarp();
    }

    if (g == 0) {
        const size_t hx = (size_t)T_STEPS * BATCH * 16;
        const float* hb = hbuf[warp][e];
        *reinterpret_cast<float4*>(&out[hx + (size_t)b * 16 + 4 * k]) =
            *reinterpret_cast<const float4*>(&hb[4 * k]);
        *reinterpret_cast<float4*>(&out[hx + (size_t)BATCH * 16 + (size_t)b * 16 + 4 * k]) =
            make_float4(c0, c1, c2, c3);
    }
}

extern "C" void kernel_launch(void* const* d_in, const int* in_sizes, int n_in,
                              void* d_out, int out_size)
{
    const float* X  = (const float*)d_in[0];
    const float* W  = (const float*)d_in[1];
    const float* bb = (const float*)d_in[2];
    const float* th = (const float*)d_in[3];
    float* out = (float*)d_out;

    const int smem = (128 * AP + 64 * AP + 64) * (int)sizeof(float);  // ~101.6 KB
    cudaFuncSetAttribute(qlstm_phase1, cudaFuncAttributeMaxDynamicSharedMemorySize, smem);
    qlstm_phase1<<<M_TOTAL / 128, 256, smem>>>(X, W, bb, th);
    qlstm_phase2<<<BATCH / (2 * NW), 256>>>(W, out);
}